// round 1
// baseline (speedup 1.0000x reference)
#include <cuda_runtime.h>

#define N_ 32
#define C_ 3
#define H_ 224
#define W_ 224
#define T_ 17   // S_+1 thetas per image

// Each thread: one (h, w4) group of 4 consecutive pixels, all 3 channels.
// gridDim.y = N_*T_ (one rotation per y-slice), gridDim.x covers H*(W/4).

__global__ __launch_bounds__(256) void rot_sample_kernel(
    const float* __restrict__ x,       // (N, C, H, W)
    const float* __restrict__ thetas,  // (N, T)
    float* __restrict__ out)           // (N, T, C, H, W)
{
    const int nt = blockIdx.y;             // 0 .. N_*T_-1
    const int n = nt / T_;

    const int idx = blockIdx.x * blockDim.x + threadIdx.x;
    const int W4 = W_ / 4;
    if (idx >= H_ * W4) return;
    const int h  = idx / W4;
    const int w4 = (idx - h * W4) * 4;

    const float theta = thetas[nt];
    float s, c;
    sincosf(theta, &s, &c);

    const float ysv = (h + 0.5f) * (2.0f / H_) - 1.0f;

    // Precompute per-pixel gather offsets + weights
    int   off00[4], off01[4], off10[4], off11[4];
    float w00[4], w01[4], w10[4], w11[4];

#pragma unroll
    for (int j = 0; j < 4; j++) {
        const int w = w4 + j;
        const float xsv = (w + 0.5f) * (2.0f / W_) - 1.0f;
        const float gx = c * xsv - s * ysv;
        const float gy = s * xsv + c * ysv;
        const float ix = ((gx + 1.0f) * W_ - 1.0f) * 0.5f;
        const float iy = ((gy + 1.0f) * H_ - 1.0f) * 0.5f;
        const float ix0f = floorf(ix);
        const float iy0f = floorf(iy);
        const float wx1 = ix - ix0f;
        const float wy1 = iy - iy0f;
        const float wx0 = 1.0f - wx1;
        const float wy0 = 1.0f - wy1;
        const int ix0 = (int)ix0f;
        const int iy0 = (int)iy0f;
        const int ix1 = ix0 + 1;
        const int iy1 = iy0 + 1;

        const bool vx0 = (ix0 >= 0) & (ix0 < W_);
        const bool vx1 = (ix1 >= 0) & (ix1 < W_);
        const bool vy0 = (iy0 >= 0) & (iy0 < H_);
        const bool vy1 = (iy1 >= 0) & (iy1 < H_);

        const int cx0 = min(max(ix0, 0), W_ - 1);
        const int cx1 = min(max(ix1, 0), W_ - 1);
        const int cy0 = min(max(iy0, 0), H_ - 1);
        const int cy1 = min(max(iy1, 0), H_ - 1);

        off00[j] = cy0 * W_ + cx0;
        off01[j] = cy0 * W_ + cx1;
        off10[j] = cy1 * W_ + cx0;
        off11[j] = cy1 * W_ + cx1;

        w00[j] = wy0 * wx0 * (float)(vy0 & vx0);
        w01[j] = wy0 * wx1 * (float)(vy0 & vx1);
        w10[j] = wy1 * wx0 * (float)(vy1 & vx0);
        w11[j] = wy1 * wx1 * (float)(vy1 & vx1);
    }

    const size_t in_n_base  = (size_t)n * C_ * H_ * W_;
    const size_t out_base   = ((size_t)nt * C_) * (H_ * W_) + (size_t)h * W_ + w4;

#pragma unroll
    for (int ch = 0; ch < C_; ch++) {
        const float* img = x + in_n_base + (size_t)ch * (H_ * W_);
        float4 r;
        float* rp = (float*)&r;
#pragma unroll
        for (int j = 0; j < 4; j++) {
            float v = __ldg(img + off00[j]) * w00[j]
                    + __ldg(img + off01[j]) * w01[j]
                    + __ldg(img + off10[j]) * w10[j]
                    + __ldg(img + off11[j]) * w11[j];
            rp[j] = v;
        }
        *reinterpret_cast<float4*>(out + out_base + (size_t)ch * (H_ * W_)) = r;
    }
}

extern "C" void kernel_launch(void* const* d_in, const int* in_sizes, int n_in,
                              void* d_out, int out_size) {
    const float* x      = (const float*)d_in[0];
    const float* thetas = (const float*)d_in[1];
    float* out          = (float*)d_out;

    const int W4 = W_ / 4;
    const int pix_groups = H_ * W4;            // 12544
    dim3 block(256);
    dim3 grid((pix_groups + 255) / 256, N_ * T_);  // (49, 544)
    rot_sample_kernel<<<grid, block>>>(x, thetas, out);
}

// round 2
// speedup vs baseline: 2.3494x; 2.3494x over previous
#include <cuda_runtime.h>

#define N_  32
#define C_  3
#define H_  224
#define W_  224
#define T_  17            // S_+1 thetas per image
#define HW_ (H_ * W_)

#define TILE_O   32       // output tile edge
#define TILE_I   48       // input tile edge (covers 32*1.366 + 2 ≈ 46)
#define TI_STR   49       // padded row stride (odd → conflict-free)

// Block: one 32x32 output tile of one (n,t) rotation, all 3 channels.
// grid.x = 49 tiles, grid.y = N_*T_ = 544.
__global__ __launch_bounds__(256) void rot_sample_tile_kernel(
    const float* __restrict__ x,       // (N, C, H, W)
    const float* __restrict__ thetas,  // (N, T)
    float* __restrict__ out)           // (N, T, C, H, W)
{
    __shared__ float tile[C_ * TILE_I * TI_STR];   // 3*48*49*4 = 28,224 B

    const int nt = blockIdx.y;
    const int n  = nt / T_;
    const int tid = threadIdx.x;

    const int tileIdx = blockIdx.x;
    const int tx0 = (tileIdx % 7) * TILE_O;
    const int ty0 = (tileIdx / 7) * TILE_O;

    const float theta = thetas[nt];
    float s, c;
    sincosf(theta, &s, &c);

    // Input-pixel-space affine map: ix = c*(w-111.5) - s*(h-111.5) + 111.5
    //                               iy = s*(w-111.5) + c*(h-111.5) + 111.5
    const float HALF = (W_ - 1) * 0.5f;   // 111.5

    // Bounding box of the 4 tile corners in input space
    const float wfa = tx0 - HALF,            wfb = tx0 + (TILE_O - 1) - HALF;
    const float hfa = ty0 - HALF,            hfb = ty0 + (TILE_O - 1) - HALF;

    float min_ix =  fminf(fminf(c * wfa - s * hfa, c * wfb - s * hfa),
                          fminf(c * wfa - s * hfb, c * wfb - s * hfb)) + HALF;
    float min_iy =  fminf(fminf(s * wfa + c * hfa, s * wfb + c * hfa),
                          fminf(s * wfa + c * hfb, s * wfb + c * hfb)) + HALF;

    const int gx0 = (int)floorf(min_ix);
    const int gy0 = (int)floorf(min_iy);

    // Cooperative tile load (clamped; garbage where weight==0 is fine)
#pragma unroll
    for (int ch = 0; ch < C_; ch++) {
        const float* img = x + ((size_t)n * C_ + ch) * HW_;
        float* t = tile + ch * (TILE_I * TI_STR);
        for (int i = tid; i < TILE_I * TILE_I; i += 256) {
            const int r  = i / TILE_I;
            const int cc = i - r * TILE_I;
            const int gr = min(max(gy0 + r,  0), H_ - 1);
            const int gc = min(max(gx0 + cc, 0), W_ - 1);
            t[r * TI_STR + cc] = __ldg(img + gr * W_ + gc);
        }
    }
    __syncthreads();

    const int tx  = tid & 31;       // output column within tile (lane)
    const int tyb = tid >> 5;       // base output row (0..7)

    const float wf = (float)(tx0 + tx) - HALF;
    const float cw = c * wf;        // hoisted across rows
    const float sw = s * wf;

    const size_t out_nt = (size_t)nt * C_ * HW_;

#pragma unroll
    for (int j = 0; j < 4; j++) {
        const int hrow = tyb + 8 * j;                  // row within tile
        const float hf = (float)(ty0 + hrow) - HALF;

        const float ix = cw - s * hf + HALF;
        const float iy = sw + c * hf + HALF;

        const float ix0f = floorf(ix);
        const float iy0f = floorf(iy);
        const float wx1 = ix - ix0f;
        const float wy1 = iy - iy0f;
        const float wx0 = 1.0f - wx1;
        const float wy0 = 1.0f - wy1;
        const int ix0 = (int)ix0f;
        const int iy0 = (int)iy0f;

        // validity in global image coords (zeros-padding semantics)
        const float vx0 = (ix0 >= 0  && ix0 < W_)      ? 1.0f : 0.0f;
        const float vx1 = (ix0 >= -1 && ix0 < W_ - 1)  ? 1.0f : 0.0f;
        const float vy0 = (iy0 >= 0  && iy0 < H_)      ? 1.0f : 0.0f;
        const float vy1 = (iy0 >= -1 && iy0 < H_ - 1)  ? 1.0f : 0.0f;

        const float w00 = wy0 * wx0 * (vy0 * vx0);
        const float w01 = wy0 * wx1 * (vy0 * vx1);
        const float w10 = wy1 * wx0 * (vy1 * vx0);
        const float w11 = wy1 * wx1 * (vy1 * vx1);

        // smem coords (clamped into tile; only weight-0 taps get clamped)
        const int col = min(max(ix0 - gx0, 0), TILE_I - 2);
        const int row = min(max(iy0 - gy0, 0), TILE_I - 2);
        const int base = row * TI_STR + col;

        const size_t out_px = out_nt + (size_t)(ty0 + hrow) * W_ + (tx0 + tx);

#pragma unroll
        for (int ch = 0; ch < C_; ch++) {
            const float* t = tile + ch * (TILE_I * TI_STR) + base;
            const float v = t[0]        * w00 + t[1]          * w01
                          + t[TI_STR]   * w10 + t[TI_STR + 1] * w11;
            out[out_px + (size_t)ch * HW_] = v;
        }
    }
}

extern "C" void kernel_launch(void* const* d_in, const int* in_sizes, int n_in,
                              void* d_out, int out_size) {
    const float* x      = (const float*)d_in[0];
    const float* thetas = (const float*)d_in[1];
    float* out          = (float*)d_out;

    dim3 block(256);
    dim3 grid(7 * 7, N_ * T_);     // 49 tiles x 544 rotations
    rot_sample_tile_kernel<<<grid, block>>>(x, thetas, out);
}